// round 11
// baseline (speedup 1.0000x reference)
#include <cuda_runtime.h>
#include <cuda_fp16.h>
#include <cstdint>
#include <math.h>

// ---------------------------------------------------------------------------
// Problem dims
// ---------------------------------------------------------------------------
#define BQ   32
#define SDIM 2048
#define DQ   512
#define MTOT (BQ * SDIM)          // 65536
#define MPAD (MTOT + 256)

// ---------------------------------------------------------------------------
// Device scratch (static only)
// ---------------------------------------------------------------------------
__device__ __align__(256) __half g_w2h[DQ * DQ];
__device__ float g_w1q[BQ * DQ];
__device__ float g_partial[2][MPAD];
__device__ int   g_rowmap[MPAD];
__device__ int   g_count;
__device__ int   g_ntiles;

// ---------------------------------------------------------------------------
// Helpers
// ---------------------------------------------------------------------------
__device__ __forceinline__ uint32_t smem_u32(const void* p) {
    uint32_t a;
    asm("{ .reg .u64 t; cvta.to.shared.u64 t, %1; cvt.u32.u64 %0, t; }" : "=r"(a) : "l"(p));
    return a;
}

__device__ __forceinline__ void ldsm4(uint32_t r[4], uint32_t addr) {
    asm volatile("ldmatrix.sync.aligned.m8n8.x4.shared.b16 {%0,%1,%2,%3}, [%4];"
                 : "=r"(r[0]), "=r"(r[1]), "=r"(r[2]), "=r"(r[3]) : "r"(addr));
}

__device__ __forceinline__ void mma_f16(float d[4], const uint32_t a[4],
                                        uint32_t b0, uint32_t b1) {
    asm volatile(
        "mma.sync.aligned.m16n8k16.row.col.f32.f16.f16.f32 "
        "{%0,%1,%2,%3}, {%4,%5,%6,%7}, {%8,%9}, {%0,%1,%2,%3};"
        : "+f"(d[0]), "+f"(d[1]), "+f"(d[2]), "+f"(d[3])
        : "r"(a[0]), "r"(a[1]), "r"(a[2]), "r"(a[3]), "r"(b0), "r"(b1));
}

#define CP_ASYNC16(sm, g) \
    asm volatile("cp.async.cg.shared.global [%0], [%1], 16;" :: "r"(sm), "l"(g))
#define CP_COMMIT()  asm volatile("cp.async.commit_group;" ::: "memory")
#define CP_WAIT0()   asm volatile("cp.async.wait_group 0;" ::: "memory")

#define STS128(addr, r0, r1, r2, r3) \
    asm volatile("st.shared.v4.b32 [%0], {%1,%2,%3,%4};" \
                 :: "r"(addr), "r"(r0), "r"(r1), "r"(r2), "r"(r3) : "memory")

// Fast accurate tanh: 1 - 2/(exp2(2*log2e*x)+1). MUFU ex2/rcp, err ~1e-6.
__device__ __forceinline__ float fast_tanh(float x) {
    float e, r;
    asm("ex2.approx.f32 %0, %1;" : "=f"(e) : "f"(x * 2.8853900817779268f));
    asm("rcp.approx.f32 %0, %1;" : "=f"(r) : "f"(e + 1.0f));
    return fmaf(-2.0f, r, 1.0f);
}

// ---------------------------------------------------------------------------
// K-PRE: heterogeneous preamble, grid = 97 blocks x 1024 threads.
//   block 0       : mask compaction (two-pass, deterministic interleaved order)
//   blocks 1..64  : convert W2 fp32 -> fp16 (8 rows per block)
//   blocks 65..96 : w1q[b][:] = query[b] . W1 (one b per block)
// ---------------------------------------------------------------------------
__global__ void __launch_bounds__(1024) preamble_kernel(const int*   __restrict__ mask,
                                                        const float* __restrict__ W2,
                                                        const float* __restrict__ query,
                                                        const float* __restrict__ W1) {
    const int blk = blockIdx.x;
    const int t   = threadIdx.x;

    if (blk == 0) {
        // ---- mask compaction: thread t owns entries t + k*1024, k=0..63 ----
        __shared__ int wsum[32];
        const int lane = t & 31, w = t >> 5;

        int cnt = 0;
#pragma unroll
        for (int k = 0; k < 64; k++) cnt += (mask[t + k * 1024] != 0);

        // inclusive warp scan of cnt
        int x = cnt;
#pragma unroll
        for (int o = 1; o < 32; o <<= 1) {
            int y = __shfl_up_sync(0xffffffffu, x, o);
            if (lane >= o) x += y;
        }
        if (lane == 31) wsum[w] = x;
        __syncthreads();
        if (t < 32) {
            int y = wsum[t];
#pragma unroll
            for (int o = 1; o < 32; o <<= 1) {
                int z = __shfl_up_sync(0xffffffffu, y, o);
                if (t >= o) y += z;
            }
            wsum[t] = y;
        }
        __syncthreads();
        int off = x - cnt + (w ? wsum[w - 1] : 0);   // exclusive offset
        const int total = wsum[31];

        if (t == 0) { g_count = total; g_ntiles = (total + 127) >> 7; }
        if (t < 256) g_rowmap[total + t] = MTOT + t; // padding -> dump zone

        // pass 2: write indices
#pragma unroll
        for (int k = 0; k < 64; k++) {
            int gi = t + k * 1024;
            if (mask[gi] != 0) g_rowmap[off++] = gi;
        }
    } else if (blk <= 64) {
        // ---- convert W2: flat half2 space 512*256; block covers 2048 ----
        const int base = (blk - 1) * 2048;
        const float2* src = (const float2*)W2;
        __half2* dst = (__half2*)g_w2h;
#pragma unroll
        for (int i = 0; i < 2; i++) {
            int e = base + t + i * 1024;
            float2 xv = src[e];
            dst[e] = __floats2half2_rn(xv.x, xv.y);
        }
    } else {
        // ---- w1q: b = blk-65; threads 0..511 each one a ----
        const int b = blk - 65;
        if (t < DQ) {
            const float4* wv = (const float4*)(W1 + (size_t)t * DQ);
            const float4* qv = (const float4*)(query + (size_t)b * DQ);
            float acc = 0.f;
#pragma unroll 8
            for (int d = 0; d < DQ / 4; d++) {
                float4 a = wv[d], q = qv[d];
                acc += a.x * q.x + a.y * q.y + a.z * q.z + a.w * q.w;
            }
            g_w1q[b * DQ + t] = acc;
        }
    }
}

// ---------------------------------------------------------------------------
// K5: fused convert + fp16x2 split GEMM over compacted rows + tanh/v epilogue.
// A path: LDG keys fp32 (rowmap gather, hoisted) -> reg split hi/lo -> STS.
// B path: cp.async from pre-converted g_w2h.
// CTA tile 128 x 256, BK=32, 512 threads / 16 warps, warp tile 64x32.
// SMEM 8x8-block-major -> conflict-free ldmatrix. Grid (2, 512), early-exit.
// ---------------------------------------------------------------------------
#define AHI 0
#define ALO 8192
#define BHI 16384
#define STAGE_B 32768
#define SMEM_TOTAL (2 * STAGE_B)

__global__ void __launch_bounds__(512, 1) gemm_kernel(const float* __restrict__ keys,
                                                      const float* __restrict__ v) {
    if ((int)blockIdx.y >= g_ntiles) return;

    extern __shared__ char smem[];
    const uint32_t sb = smem_u32(smem);
    const int tid = threadIdx.x;
    const int wid = tid >> 5, lane = tid & 31;
    const int mw  = wid & 1;
    const int nwp = wid >> 1;
    const int row0 = blockIdx.y * 128;
    const int col0 = blockIdx.x * 256;

    const uint32_t laneA = (((lane & 15) >> 3) << 9) + ((lane >> 4) << 7) + ((lane & 7) << 4);

    // hoisted A-gather: thread owns (row = tid>>2, kb = tid&3)
    const int arow = tid >> 2, akb = tid & 3;
    int orig = g_rowmap[row0 + arow];
    if (orig > MTOT - 1) orig = MTOT - 1;
    const float4* aptr = (const float4*)(keys + (size_t)orig * DQ + akb * 8);
    const uint32_t asts = sb + ((arow >> 3) * 4 + akb) * 128 + ((arow & 7) << 4);

    float acc[4][4][4];
#pragma unroll
    for (int i = 0; i < 4; i++)
#pragma unroll
        for (int j = 0; j < 4; j++)
#pragma unroll
            for (int k = 0; k < 4; k++) acc[i][j][k] = 0.f;

    auto loadA = [&](int c, uint32_t h[4], uint32_t l[4]) {
        float4 x0 = aptr[c * 8];
        float4 x1 = aptr[c * 8 + 1];
        float f[8] = {x0.x, x0.y, x0.z, x0.w, x1.x, x1.y, x1.z, x1.w};
#pragma unroll
        for (int i = 0; i < 4; i++) {
            __half2 hh = __floats2half2_rn(f[2 * i], f[2 * i + 1]);
            float2 hf = __half22float2(hh);
            __half2 ll = __floats2half2_rn(f[2 * i] - hf.x, f[2 * i + 1] - hf.y);
            h[i] = *reinterpret_cast<unsigned*>(&hh);
            l[i] = *reinterpret_cast<unsigned*>(&ll);
        }
    };

    auto loadB = [&](int c, int s) {
        const uint32_t sbase = sb + s * STAGE_B;
        const size_t kof = (size_t)c * 32;
#pragma unroll
        for (int i = 0; i < 2; i++) {
            int u = tid + i * 512;
            int row = u >> 2, kb = u & 3;
            size_t gi = (size_t)(col0 + row) * DQ + kof + kb * 8;
            uint32_t sm = sbase + ((row >> 3) * 4 + kb) * 128 + ((row & 7) << 4);
            CP_ASYNC16(sm + BHI, g_w2h + gi);
        }
    };

    uint32_t hA[4], lA[4], hN[4], lN[4];
    loadA(0, hA, lA);
    loadB(0, 0);
    CP_COMMIT();

#pragma unroll 1
    for (int c = 0; c < 16; c++) {
        const int s = c & 1;
        const uint32_t stg = sb + s * STAGE_B;

        CP_WAIT0();
        STS128(asts + s * STAGE_B + AHI, hA[0], hA[1], hA[2], hA[3]);
        STS128(asts + s * STAGE_B + ALO, lA[0], lA[1], lA[2], lA[3]);
        __syncthreads();

        if (c < 15) {
            loadB(c + 1, s ^ 1);
            CP_COMMIT();
            loadA(c + 1, hN, lN);
        }

#pragma unroll
        for (int kt = 0; kt < 2; kt++) {
            const uint32_t abase = stg + laneA + mw * 4096 + kt * 256;
            const uint32_t bbase = stg + laneA + nwp * 2048 + kt * 256;

            uint32_t ah[4][4], bh[2][4];
#pragma unroll
            for (int mt = 0; mt < 4; mt++) ldsm4(ah[mt], abase + AHI + mt * 1024);
#pragma unroll
            for (int pb = 0; pb < 2; pb++) ldsm4(bh[pb], bbase + BHI + pb * 1024);

#pragma unroll
            for (int mt = 0; mt < 4; mt++)
#pragma unroll
                for (int pb = 0; pb < 2; pb++) {
                    mma_f16(acc[mt][2 * pb],     ah[mt], bh[pb][0], bh[pb][2]);
                    mma_f16(acc[mt][2 * pb + 1], ah[mt], bh[pb][1], bh[pb][3]);
                }

            uint32_t al[4][4];
#pragma unroll
            for (int mt = 0; mt < 4; mt++) ldsm4(al[mt], abase + ALO + mt * 1024);
#pragma unroll
            for (int mt = 0; mt < 4; mt++)
#pragma unroll
                for (int pb = 0; pb < 2; pb++) {
                    mma_f16(acc[mt][2 * pb],     al[mt], bh[pb][0], bh[pb][2]);
                    mma_f16(acc[mt][2 * pb + 1], al[mt], bh[pb][1], bh[pb][3]);
                }
        }

#pragma unroll
        for (int i = 0; i < 4; i++) { hA[i] = hN[i]; lA[i] = lN[i]; }
    }

    // ---- epilogue: tanh(acc + w1q) * v, reduce N, scatter via rowmap ----
    const int q = lane >> 2;
    float* red = (float*)smem;
    __syncthreads();

#pragma unroll
    for (int mt = 0; mt < 4; mt++) {
        int r_lo = row0 + mw * 64 + mt * 16 + q;
        int r_hi = r_lo + 8;
        int b_lo = g_rowmap[r_lo] >> 11;
        int b_hi = g_rowmap[r_hi] >> 11;
        if (b_lo > BQ - 1) b_lo = BQ - 1;
        if (b_hi > BQ - 1) b_hi = BQ - 1;
        float p0 = 0.f, p1 = 0.f;
#pragma unroll
        for (int n8 = 0; n8 < 4; n8++) {
            int cg = col0 + nwp * 32 + n8 * 8 + (lane & 3) * 2;
            float2 w1a = *(const float2*)(g_w1q + b_lo * DQ + cg);
            float2 w1b = *(const float2*)(g_w1q + b_hi * DQ + cg);
            float2 vv = *(const float2*)(v + cg);
            float* d = acc[mt][n8];
            p0 += fast_tanh(d[0] + w1a.x) * vv.x + fast_tanh(d[1] + w1a.y) * vv.y;
            p1 += fast_tanh(d[2] + w1b.x) * vv.x + fast_tanh(d[3] + w1b.y) * vv.y;
        }
        p0 += __shfl_xor_sync(0xffffffff, p0, 1);
        p0 += __shfl_xor_sync(0xffffffff, p0, 2);
        p1 += __shfl_xor_sync(0xffffffff, p1, 1);
        p1 += __shfl_xor_sync(0xffffffff, p1, 2);
        if ((lane & 3) == 0) {
            int r = mw * 64 + mt * 16 + q;
            red[nwp * 128 + r]     = p0;
            red[nwp * 128 + r + 8] = p1;
        }
    }
    __syncthreads();
    if (tid < 128) {
        float s = 0.f;
#pragma unroll
        for (int w = 0; w < 8; w++) s += red[w * 128 + tid];
        g_partial[blockIdx.x][g_rowmap[row0 + tid]] = s;
    }
}

// ---------------------------------------------------------------------------
// K6: masked softmax (mask int32). One block per batch row.
// ---------------------------------------------------------------------------
__global__ void __launch_bounds__(256) softmax_kernel(const int* __restrict__ mask,
                                                      float* __restrict__ out) {
    const int b = blockIdx.x, tid = threadIdx.x;
    __shared__ float red[256];

    float vals[8];
    float mx = -INFINITY;
#pragma unroll
    for (int t = 0; t < 8; t++) {
        int gi = b * SDIM + tid + t * 256;
        float sc = g_partial[0][gi] + g_partial[1][gi];
        sc = mask[gi] ? sc : -INFINITY;
        vals[t] = sc;
        mx = fmaxf(mx, sc);
    }
    red[tid] = mx;
    __syncthreads();
    for (int o = 128; o; o >>= 1) {
        if (tid < o) red[tid] = fmaxf(red[tid], red[tid + o]);
        __syncthreads();
    }
    mx = red[0];
    __syncthreads();

    float sum = 0.f;
#pragma unroll
    for (int t = 0; t < 8; t++) {
        vals[t] = expf(vals[t] - mx);
        sum += vals[t];
    }
    red[tid] = sum;
    __syncthreads();
    for (int o = 128; o; o >>= 1) {
        if (tid < o) red[tid] += red[tid + o];
        __syncthreads();
    }
    float inv = 1.f / red[0];
#pragma unroll
    for (int t = 0; t < 8; t++) out[b * SDIM + tid + t * 256] = vals[t] * inv;
}

// ---------------------------------------------------------------------------
// Launch: 3 kernels total.
// ---------------------------------------------------------------------------
extern "C" void kernel_launch(void* const* d_in, const int* in_sizes, int n_in,
                              void* d_out, int out_size) {
    const float* query = (const float*)d_in[0];
    const float* keys  = (const float*)d_in[1];
    const int*   mask  = (const int*)d_in[2];
    const float* W1    = (const float*)d_in[3];
    const float* W2    = (const float*)d_in[4];
    const float* v     = (const float*)d_in[5];
    float*       out   = (float*)d_out;

    static bool attr_set = false;
    if (!attr_set) {
        cudaFuncSetAttribute(gemm_kernel, cudaFuncAttributeMaxDynamicSharedMemorySize,
                             SMEM_TOTAL);
        attr_set = true;
    }

    preamble_kernel<<<97, 1024>>>(mask, W2, query, W1);
    gemm_kernel<<<dim3(2, 512), 512, SMEM_TOTAL>>>(keys, v);
    softmax_kernel<<<BQ, 256>>>(mask, out);
}

// round 12
// speedup vs baseline: 1.4867x; 1.4867x over previous
#include <cuda_runtime.h>
#include <cuda_fp16.h>
#include <cstdint>
#include <math.h>

// ---------------------------------------------------------------------------
// Problem dims
// ---------------------------------------------------------------------------
#define BQ   32
#define SDIM 2048
#define DQ   512
#define MTOT (BQ * SDIM)          // 65536
#define MPAD (MTOT + 256)

// ---------------------------------------------------------------------------
// Device scratch (static only)
// ---------------------------------------------------------------------------
__device__ __align__(256) __half g_w2h[DQ * DQ];
__device__ float g_w1q[BQ * DQ];
__device__ float g_partial[2][MPAD];
__device__ int   g_rowmap[MPAD];
__device__ int   g_blockcnt[256];
__device__ int   g_blockoff[256];
__device__ int   g_count;
__device__ int   g_ntiles;

// ---------------------------------------------------------------------------
// Helpers
// ---------------------------------------------------------------------------
__device__ __forceinline__ uint32_t smem_u32(const void* p) {
    uint32_t a;
    asm("{ .reg .u64 t; cvta.to.shared.u64 t, %1; cvt.u32.u64 %0, t; }" : "=r"(a) : "l"(p));
    return a;
}

__device__ __forceinline__ void ldsm4(uint32_t r[4], uint32_t addr) {
    asm volatile("ldmatrix.sync.aligned.m8n8.x4.shared.b16 {%0,%1,%2,%3}, [%4];"
                 : "=r"(r[0]), "=r"(r[1]), "=r"(r[2]), "=r"(r[3]) : "r"(addr));
}

__device__ __forceinline__ void mma_f16(float d[4], const uint32_t a[4],
                                        uint32_t b0, uint32_t b1) {
    asm volatile(
        "mma.sync.aligned.m16n8k16.row.col.f32.f16.f16.f32 "
        "{%0,%1,%2,%3}, {%4,%5,%6,%7}, {%8,%9}, {%0,%1,%2,%3};"
        : "+f"(d[0]), "+f"(d[1]), "+f"(d[2]), "+f"(d[3])
        : "r"(a[0]), "r"(a[1]), "r"(a[2]), "r"(a[3]), "r"(b0), "r"(b1));
}

#define CP_ASYNC16(sm, g) \
    asm volatile("cp.async.cg.shared.global [%0], [%1], 16;" :: "r"(sm), "l"(g))
#define CP_COMMIT()  asm volatile("cp.async.commit_group;" ::: "memory")
#define CP_WAIT0()   asm volatile("cp.async.wait_group 0;" ::: "memory")

#define STS128(addr, r0, r1, r2, r3) \
    asm volatile("st.shared.v4.b32 [%0], {%1,%2,%3,%4};" \
                 :: "r"(addr), "r"(r0), "r"(r1), "r"(r2), "r"(r3) : "memory")

// Fast accurate tanh: 1 - 2/(exp2(2*log2e*x)+1). MUFU ex2/rcp, err ~1e-6.
__device__ __forceinline__ float fast_tanh(float x) {
    float e, r;
    asm("ex2.approx.f32 %0, %1;" : "=f"(e) : "f"(x * 2.8853900817779268f));
    asm("rcp.approx.f32 %0, %1;" : "=f"(r) : "f"(e + 1.0f));
    return fmaf(-2.0f, r, 1.0f);
}

// ---------------------------------------------------------------------------
// K0: per-256-block mask popcount
// ---------------------------------------------------------------------------
__global__ void __launch_bounds__(256) mask_count(const int* __restrict__ mask) {
    int t = threadIdx.x, b = blockIdx.x;
    int m = mask[b * 256 + t] != 0;
    unsigned bal = __ballot_sync(0xffffffffu, m);
    __shared__ int ws[8];
    if ((t & 31) == 0) ws[t >> 5] = __popc(bal);
    __syncthreads();
    if (t == 0) {
        int s = 0;
#pragma unroll
        for (int i = 0; i < 8; i++) s += ws[i];
        g_blockcnt[b] = s;
    }
}

// ---------------------------------------------------------------------------
// K1: scan block counts, publish offsets/count/ntiles, fill padding map
// ---------------------------------------------------------------------------
__global__ void __launch_bounds__(256) mask_scan() {
    __shared__ int sh[256];
    int t = threadIdx.x;
    int v = g_blockcnt[t];
    sh[t] = v;
    __syncthreads();
    for (int o = 1; o < 256; o <<= 1) {
        int x = (t >= o) ? sh[t - o] : 0;
        __syncthreads();
        sh[t] += x;
        __syncthreads();
    }
    g_blockoff[t] = sh[t] - v;
    int total = sh[255];
    if (t == 0) { g_count = total; g_ntiles = (total + 127) >> 7; }
    g_rowmap[total + t] = MTOT + t;   // padding rows -> dump zone
}

// ---------------------------------------------------------------------------
// K2: scatter unmasked original row indices into g_rowmap (stable order)
// ---------------------------------------------------------------------------
__global__ void __launch_bounds__(256) mask_scatter(const int* __restrict__ mask) {
    int t = threadIdx.x, b = blockIdx.x, lane = t & 31, w = t >> 5;
    int m = mask[b * 256 + t] != 0;
    unsigned bal = __ballot_sync(0xffffffffu, m);
    __shared__ int ws[8];
    if (lane == 0) ws[w] = __popc(bal);
    __syncthreads();
    int wb = 0;
    for (int i = 0; i < w; i++) wb += ws[i];
    int rank = g_blockoff[b] + wb + __popc(bal & ((1u << lane) - 1u));
    if (m) g_rowmap[rank] = b * 256 + t;
}

// ---------------------------------------------------------------------------
// K3: convert W2 (fp32 -> fp16). One row per block.
// ---------------------------------------------------------------------------
__global__ void __launch_bounds__(256) convert_w2(const float* __restrict__ W2) {
    int r = blockIdx.x, t = threadIdx.x;
    float2 x = ((const float2*)(W2 + (size_t)r * DQ))[t];
    ((__half2*)g_w2h)[r * 256 + t] = __floats2half2_rn(x.x, x.y);
}

// ---------------------------------------------------------------------------
// K4: w1q[b][a] = query[b] . W1[a]
// ---------------------------------------------------------------------------
__global__ void __launch_bounds__(128) w1q_kernel(const float* __restrict__ query,
                                                  const float* __restrict__ W1) {
    int a = blockIdx.x * 128 + threadIdx.x;
    int b = blockIdx.y;
    const float4* w = (const float4*)(W1 + (size_t)a * DQ);
    const float4* q = (const float4*)(query + (size_t)b * DQ);
    float acc = 0.f;
#pragma unroll 8
    for (int d = 0; d < DQ / 4; d++) {
        float4 wv = w[d], qv = q[d];
        acc += wv.x * qv.x + wv.y * qv.y + wv.z * qv.z + wv.w * qv.w;
    }
    g_w1q[b * DQ + a] = acc;
}

// ---------------------------------------------------------------------------
// K5: fused convert + 1-term fp16 GEMM over compacted rows + tanh/v epilogue.
// A path: LDG keys fp32 (rowmap gather, hoisted) -> cvt fp16 -> STS.
// B path: cp.async from pre-converted g_w2h.
// CTA tile 128 x 256, BK=32, 512 threads / 16 warps, warp tile 64x32.
// SMEM 8x8-block-major -> conflict-free ldmatrix. Grid (2, 512), early-exit.
// ---------------------------------------------------------------------------
#define AHI 0
#define BHI 8192
#define STAGE_B 24576
#define SMEM_TOTAL (2 * STAGE_B)

__global__ void __launch_bounds__(512, 1) gemm_kernel(const float* __restrict__ keys,
                                                      const float* __restrict__ v) {
    if ((int)blockIdx.y >= g_ntiles) return;

    extern __shared__ char smem[];
    const uint32_t sb = smem_u32(smem);
    const int tid = threadIdx.x;
    const int wid = tid >> 5, lane = tid & 31;
    const int mw  = wid & 1;
    const int nwp = wid >> 1;
    const int row0 = blockIdx.y * 128;
    const int col0 = blockIdx.x * 256;

    const uint32_t laneA = (((lane & 15) >> 3) << 9) + ((lane >> 4) << 7) + ((lane & 7) << 4);

    // hoisted A-gather: thread owns (row = tid>>2, kb = tid&3)
    const int arow = tid >> 2, akb = tid & 3;
    int orig = g_rowmap[row0 + arow];
    if (orig > MTOT - 1) orig = MTOT - 1;
    const float4* aptr = (const float4*)(keys + (size_t)orig * DQ + akb * 8);
    const uint32_t asts = sb + ((arow >> 3) * 4 + akb) * 128 + ((arow & 7) << 4);

    float acc[4][4][4];
#pragma unroll
    for (int i = 0; i < 4; i++)
#pragma unroll
        for (int j = 0; j < 4; j++)
#pragma unroll
            for (int k = 0; k < 4; k++) acc[i][j][k] = 0.f;

    // load 8 fp32 of chunk c -> 4 fp16x2 regs
    auto loadA = [&](int c, uint32_t h[4]) {
        float4 x0 = aptr[c * 8];
        float4 x1 = aptr[c * 8 + 1];
        float f[8] = {x0.x, x0.y, x0.z, x0.w, x1.x, x1.y, x1.z, x1.w};
#pragma unroll
        for (int i = 0; i < 4; i++) {
            __half2 hh = __floats2half2_rn(f[2 * i], f[2 * i + 1]);
            h[i] = *reinterpret_cast<unsigned*>(&hh);
        }
    };

    auto loadB = [&](int c, int s) {
        const uint32_t sbase = sb + s * STAGE_B;
        const size_t kof = (size_t)c * 32;
#pragma unroll
        for (int i = 0; i < 2; i++) {
            int u = tid + i * 512;
            int row = u >> 2, kb = u & 3;
            size_t gi = (size_t)(col0 + row) * DQ + kof + kb * 8;
            uint32_t sm = sbase + ((row >> 3) * 4 + kb) * 128 + ((row & 7) << 4);
            CP_ASYNC16(sm + BHI, g_w2h + gi);
        }
    };

    uint32_t hA[4], hN[4];
    loadA(0, hA);
    loadB(0, 0);
    CP_COMMIT();

#pragma unroll 1
    for (int c = 0; c < 16; c++) {
        const int s = c & 1;
        const uint32_t stg = sb + s * STAGE_B;

        CP_WAIT0();                                   // B(c) resident
        STS128(asts + s * STAGE_B + AHI, hA[0], hA[1], hA[2], hA[3]);
        __syncthreads();                              // orders STS/cp.async vs LDSM

        if (c < 15) {
            loadB(c + 1, s ^ 1);                      // stage s^1 drained at sync
            CP_COMMIT();
            loadA(c + 1, hN);                         // LDG hides under MMAs
        }

#pragma unroll
        for (int kt = 0; kt < 2; kt++) {
            const uint32_t abase = stg + laneA + mw * 4096 + kt * 256;
            const uint32_t bbase = stg + laneA + nwp * 2048 + kt * 256;

            uint32_t ah[4][4], bh[2][4];
#pragma unroll
            for (int mt = 0; mt < 4; mt++) ldsm4(ah[mt], abase + AHI + mt * 1024);
#pragma unroll
            for (int pb = 0; pb < 2; pb++) ldsm4(bh[pb], bbase + BHI + pb * 1024);

#pragma unroll
            for (int mt = 0; mt < 4; mt++)
#pragma unroll
                for (int pb = 0; pb < 2; pb++) {
                    mma_f16(acc[mt][2 * pb],     ah[mt], bh[pb][0], bh[pb][2]);
                    mma_f16(acc[mt][2 * pb + 1], ah[mt], bh[pb][1], bh[pb][3]);
                }
        }

#pragma unroll
        for (int i = 0; i < 4; i++) hA[i] = hN[i];
    }

    // ---- epilogue: tanh(acc + w1q) * v, reduce N, scatter via rowmap ----
    const int q = lane >> 2;
    float* red = (float*)smem;
    __syncthreads();

#pragma unroll
    for (int mt = 0; mt < 4; mt++) {
        int r_lo = row0 + mw * 64 + mt * 16 + q;
        int r_hi = r_lo + 8;
        int b_lo = g_rowmap[r_lo] >> 11;
        int b_hi = g_rowmap[r_hi] >> 11;
        if (b_lo > BQ - 1) b_lo = BQ - 1;
        if (b_hi > BQ - 1) b_hi = BQ - 1;
        float p0 = 0.f, p1 = 0.f;
#pragma unroll
        for (int n8 = 0; n8 < 4; n8++) {
            int cg = col0 + nwp * 32 + n8 * 8 + (lane & 3) * 2;
            float2 w1a = *(const float2*)(g_w1q + b_lo * DQ + cg);
            float2 w1b = *(const float2*)(g_w1q + b_hi * DQ + cg);
            float2 vv = *(const float2*)(v + cg);
            float* d = acc[mt][n8];
            p0 += fast_tanh(d[0] + w1a.x) * vv.x + fast_tanh(d[1] + w1a.y) * vv.y;
            p1 += fast_tanh(d[2] + w1b.x) * vv.x + fast_tanh(d[3] + w1b.y) * vv.y;
        }
        p0 += __shfl_xor_sync(0xffffffff, p0, 1);
        p0 += __shfl_xor_sync(0xffffffff, p0, 2);
        p1 += __shfl_xor_sync(0xffffffff, p1, 1);
        p1 += __shfl_xor_sync(0xffffffff, p1, 2);
        if ((lane & 3) == 0) {
            int r = mw * 64 + mt * 16 + q;
            red[nwp * 128 + r]     = p0;
            red[nwp * 128 + r + 8] = p1;
        }
    }
    __syncthreads();
    if (tid < 128) {
        float s = 0.f;
#pragma unroll
        for (int w = 0; w < 8; w++) s += red[w * 128 + tid];
        g_partial[blockIdx.x][g_rowmap[row0 + tid]] = s;
    }
}

// ---------------------------------------------------------------------------
// K6: masked softmax (mask int32). One block per batch row.
// ---------------------------------------------------------------------------
__global__ void __launch_bounds__(256) softmax_kernel(const int* __restrict__ mask,
                                                      float* __restrict__ out) {
    const int b = blockIdx.x, tid = threadIdx.x;
    __shared__ float red[256];

    float vals[8];
    float mx = -INFINITY;
#pragma unroll
    for (int t = 0; t < 8; t++) {
        int gi = b * SDIM + tid + t * 256;
        float sc = g_partial[0][gi] + g_partial[1][gi];
        sc = mask[gi] ? sc : -INFINITY;
        vals[t] = sc;
        mx = fmaxf(mx, sc);
    }
    red[tid] = mx;
    __syncthreads();
    for (int o = 128; o; o >>= 1) {
        if (tid < o) red[tid] = fmaxf(red[tid], red[tid + o]);
        __syncthreads();
    }
    mx = red[0];
    __syncthreads();

    float sum = 0.f;
#pragma unroll
    for (int t = 0; t < 8; t++) {
        vals[t] = expf(vals[t] - mx);
        sum += vals[t];
    }
    red[tid] = sum;
    __syncthreads();
    for (int o = 128; o; o >>= 1) {
        if (tid < o) red[tid] += red[tid + o];
        __syncthreads();
    }
    float inv = 1.f / red[0];
#pragma unroll
    for (int t = 0; t < 8; t++) out[b * SDIM + tid + t * 256] = vals[t] * inv;
}

// ---------------------------------------------------------------------------
// Launch
// ---------------------------------------------------------------------------
extern "C" void kernel_launch(void* const* d_in, const int* in_sizes, int n_in,
                              void* d_out, int out_size) {
    const float* query = (const float*)d_in[0];
    const float* keys  = (const float*)d_in[1];
    const int*   mask  = (const int*)d_in[2];
    const float* W1    = (const float*)d_in[3];
    const float* W2    = (const float*)d_in[4];
    const float* v     = (const float*)d_in[5];
    float*       out   = (float*)d_out;

    static bool attr_set = false;
    if (!attr_set) {
        cudaFuncSetAttribute(gemm_kernel, cudaFuncAttributeMaxDynamicSharedMemorySize,
                             SMEM_TOTAL);
        attr_set = true;
    }

    mask_count<<<256, 256>>>(mask);
    mask_scan<<<1, 256>>>();
    mask_scatter<<<256, 256>>>(mask);
    convert_w2<<<512, 256>>>(W2);
    w1q_kernel<<<dim3(4, BQ), 128>>>(query, W1);
    gemm_kernel<<<dim3(2, 512), 512, SMEM_TOTAL>>>(keys, v);
    softmax_kernel<<<BQ, 256>>>(mask, out);
}

// round 13
// speedup vs baseline: 1.4900x; 1.0022x over previous
#include <cuda_runtime.h>
#include <cuda_fp16.h>
#include <cstdint>
#include <math.h>

// ---------------------------------------------------------------------------
// Problem dims
// ---------------------------------------------------------------------------
#define BQ   32
#define SDIM 2048
#define DQ   512
#define MTOT (BQ * SDIM)          // 65536
#define MPAD (MTOT + 256)

// ---------------------------------------------------------------------------
// Device scratch (static only)
// ---------------------------------------------------------------------------
__device__ __align__(256) __half g_w2h[DQ * DQ];
__device__ float g_w1q[BQ * DQ];
__device__ float g_partial[2][MPAD];
__device__ int   g_rowmap[MPAD];
__device__ int   g_blockcnt[256];
__device__ int   g_count;
__device__ int   g_ntiles;

// ---------------------------------------------------------------------------
// Helpers
// ---------------------------------------------------------------------------
__device__ __forceinline__ uint32_t smem_u32(const void* p) {
    uint32_t a;
    asm("{ .reg .u64 t; cvta.to.shared.u64 t, %1; cvt.u32.u64 %0, t; }" : "=r"(a) : "l"(p));
    return a;
}

__device__ __forceinline__ void ldsm4(uint32_t r[4], uint32_t addr) {
    asm volatile("ldmatrix.sync.aligned.m8n8.x4.shared.b16 {%0,%1,%2,%3}, [%4];"
                 : "=r"(r[0]), "=r"(r[1]), "=r"(r[2]), "=r"(r[3]) : "r"(addr));
}

__device__ __forceinline__ void mma_f16(float d[4], const uint32_t a[4],
                                        uint32_t b0, uint32_t b1) {
    asm volatile(
        "mma.sync.aligned.m16n8k16.row.col.f32.f16.f16.f32 "
        "{%0,%1,%2,%3}, {%4,%5,%6,%7}, {%8,%9}, {%0,%1,%2,%3};"
        : "+f"(d[0]), "+f"(d[1]), "+f"(d[2]), "+f"(d[3])
        : "r"(a[0]), "r"(a[1]), "r"(a[2]), "r"(a[3]), "r"(b0), "r"(b1));
}

#define CP_ASYNC16(sm, g) \
    asm volatile("cp.async.cg.shared.global [%0], [%1], 16;" :: "r"(sm), "l"(g))
#define CP_COMMIT()  asm volatile("cp.async.commit_group;" ::: "memory")
#define CP_WAIT0()   asm volatile("cp.async.wait_group 0;" ::: "memory")

#define STS128(addr, r0, r1, r2, r3) \
    asm volatile("st.shared.v4.b32 [%0], {%1,%2,%3,%4};" \
                 :: "r"(addr), "r"(r0), "r"(r1), "r"(r2), "r"(r3) : "memory")

// Fast accurate tanh: 1 - 2/(exp2(2*log2e*x)+1). MUFU ex2/rcp, err ~1e-6.
__device__ __forceinline__ float fast_tanh(float x) {
    float e, r;
    asm("ex2.approx.f32 %0, %1;" : "=f"(e) : "f"(x * 2.8853900817779268f));
    asm("rcp.approx.f32 %0, %1;" : "=f"(r) : "f"(e + 1.0f));
    return fmaf(-2.0f, r, 1.0f);
}

// ---------------------------------------------------------------------------
// K-PRE1: heterogeneous parallel preamble, 832 blocks x 256 threads.
//   blocks   0..255 : mask popcount per 256-elt chunk -> g_blockcnt
//   blocks 256..767 : convert W2 fp32 -> fp16 (one row per block)
//   blocks 768..831 : w1q (one (b, 256-wide a-segment) per block)
// All blocks are small & uniform -> no serial long pole (round-11 lesson).
// ---------------------------------------------------------------------------
__global__ void __launch_bounds__(256) pre1_kernel(const int*   __restrict__ mask,
                                                   const float* __restrict__ W2,
                                                   const float* __restrict__ query,
                                                   const float* __restrict__ W1) {
    const int blk = blockIdx.x, t = threadIdx.x;

    if (blk < 256) {
        int m = mask[blk * 256 + t] != 0;
        unsigned bal = __ballot_sync(0xffffffffu, m);
        __shared__ int ws[8];
        if ((t & 31) == 0) ws[t >> 5] = __popc(bal);
        __syncthreads();
        if (t == 0) {
            int s = 0;
#pragma unroll
            for (int i = 0; i < 8; i++) s += ws[i];
            g_blockcnt[blk] = s;
        }
    } else if (blk < 768) {
        int r = blk - 256;
        float2 x = ((const float2*)(W2 + (size_t)r * DQ))[t];
        ((__half2*)g_w2h)[r * 256 + t] = __floats2half2_rn(x.x, x.y);
    } else {
        int idx = blk - 768;                 // 0..63
        int b = idx >> 1;
        int a = ((idx & 1) << 8) + t;        // 256-wide segment
        const float4* wv = (const float4*)(W1 + (size_t)a * DQ);
        const float4* qv = (const float4*)(query + (size_t)b * DQ);
        float acc = 0.f;
#pragma unroll 8
        for (int d = 0; d < DQ / 4; d++) {
            float4 w = wv[d], q = qv[d];
            acc += w.x * q.x + w.y * q.y + w.z * q.z + w.w * q.w;
        }
        g_w1q[b * DQ + a] = acc;
    }
}

// ---------------------------------------------------------------------------
// K-PRE2: scan + scatter fused. 256 blocks x 256 threads.
// Every block redundantly scans the 256-entry count array (cheap, L2-hot),
// then block b scatters its own 256 mask entries. Block 0 publishes
// count/ntiles and pads the rowmap tail.
// ---------------------------------------------------------------------------
__global__ void __launch_bounds__(256) pre2_kernel(const int* __restrict__ mask) {
    __shared__ int sh[256];
    const int b = blockIdx.x, t = threadIdx.x, lane = t & 31, w = t >> 5;

    int v = g_blockcnt[t];
    sh[t] = v;
    __syncthreads();
    for (int o = 1; o < 256; o <<= 1) {
        int x = (t >= o) ? sh[t - o] : 0;
        __syncthreads();
        sh[t] += x;
        __syncthreads();
    }
    const int total = sh[255];
    const int blockoff = (b == 0) ? 0 : sh[b - 1];

    if (b == 0) {
        if (t == 0) { g_count = total; g_ntiles = (total + 127) >> 7; }
        g_rowmap[total + t] = MTOT + t;      // padding rows -> dump zone
    }

    int m = mask[b * 256 + t] != 0;
    unsigned bal = __ballot_sync(0xffffffffu, m);
    __shared__ int ws[8];
    if (lane == 0) ws[w] = __popc(bal);
    __syncthreads();
    int wb = 0;
    for (int i = 0; i < w; i++) wb += ws[i];
    int rank = blockoff + wb + __popc(bal & ((1u << lane) - 1u));
    if (m) g_rowmap[rank] = b * 256 + t;
}

// ---------------------------------------------------------------------------
// K5: fused convert + 1-term fp16 GEMM over compacted rows + tanh/v epilogue.
// A path: LDG keys fp32 (rowmap gather, hoisted) -> cvt fp16 -> STS.
// B path: cp.async from pre-converted g_w2h.
// CTA tile 128 x 256, BK=32, 512 threads / 16 warps, warp tile 64x32.
// SMEM 8x8-block-major -> conflict-free ldmatrix. Grid (2, 512), early-exit.
// ---------------------------------------------------------------------------
#define AHI 0
#define BHI 8192
#define STAGE_B 24576
#define SMEM_TOTAL (2 * STAGE_B)

__global__ void __launch_bounds__(512, 1) gemm_kernel(const float* __restrict__ keys,
                                                      const float* __restrict__ v) {
    if ((int)blockIdx.y >= g_ntiles) return;

    extern __shared__ char smem[];
    const uint32_t sb = smem_u32(smem);
    const int tid = threadIdx.x;
    const int wid = tid >> 5, lane = tid & 31;
    const int mw  = wid & 1;
    const int nwp = wid >> 1;
    const int row0 = blockIdx.y * 128;
    const int col0 = blockIdx.x * 256;

    const uint32_t laneA = (((lane & 15) >> 3) << 9) + ((lane >> 4) << 7) + ((lane & 7) << 4);

    // hoisted A-gather: thread owns (row = tid>>2, kb = tid&3)
    const int arow = tid >> 2, akb = tid & 3;
    int orig = g_rowmap[row0 + arow];
    if (orig > MTOT - 1) orig = MTOT - 1;
    const float4* aptr = (const float4*)(keys + (size_t)orig * DQ + akb * 8);
    const uint32_t asts = sb + ((arow >> 3) * 4 + akb) * 128 + ((arow & 7) << 4);

    float acc[4][4][4];
#pragma unroll
    for (int i = 0; i < 4; i++)
#pragma unroll
        for (int j = 0; j < 4; j++)
#pragma unroll
            for (int k = 0; k < 4; k++) acc[i][j][k] = 0.f;

    auto loadA = [&](int c, uint32_t h[4]) {
        float4 x0 = aptr[c * 8];
        float4 x1 = aptr[c * 8 + 1];
        float f[8] = {x0.x, x0.y, x0.z, x0.w, x1.x, x1.y, x1.z, x1.w};
#pragma unroll
        for (int i = 0; i < 4; i++) {
            __half2 hh = __floats2half2_rn(f[2 * i], f[2 * i + 1]);
            h[i] = *reinterpret_cast<unsigned*>(&hh);
        }
    };

    auto loadB = [&](int c, int s) {
        const uint32_t sbase = sb + s * STAGE_B;
        const size_t kof = (size_t)c * 32;
#pragma unroll
        for (int i = 0; i < 2; i++) {
            int u = tid + i * 512;
            int row = u >> 2, kb = u & 3;
            size_t gi = (size_t)(col0 + row) * DQ + kof + kb * 8;
            uint32_t sm = sbase + ((row >> 3) * 4 + kb) * 128 + ((row & 7) << 4);
            CP_ASYNC16(sm + BHI, g_w2h + gi);
        }
    };

    uint32_t hA[4], hN[4];
    loadA(0, hA);
    loadB(0, 0);
    CP_COMMIT();

#pragma unroll 1
    for (int c = 0; c < 16; c++) {
        const int s = c & 1;
        const uint32_t stg = sb + s * STAGE_B;

        // STS first (independent of B's arrival), then drain B(c).
        STS128(asts + s * STAGE_B + AHI, hA[0], hA[1], hA[2], hA[3]);
        CP_WAIT0();
        __syncthreads();                              // orders STS/cp.async vs LDSM

        if (c < 15) {
            loadB(c + 1, s ^ 1);                      // stage s^1 drained at sync
            CP_COMMIT();
            loadA(c + 1, hN);                         // LDG hides under MMAs
        }

#pragma unroll
        for (int kt = 0; kt < 2; kt++) {
            const uint32_t abase = stg + laneA + mw * 4096 + kt * 256;
            const uint32_t bbase = stg + laneA + nwp * 2048 + kt * 256;

            uint32_t ah[4][4], bh[2][4];
#pragma unroll
            for (int mt = 0; mt < 4; mt++) ldsm4(ah[mt], abase + AHI + mt * 1024);
#pragma unroll
            for (int pb = 0; pb < 2; pb++) ldsm4(bh[pb], bbase + BHI + pb * 1024);

#pragma unroll
            for (int mt = 0; mt < 4; mt++)
#pragma unroll
                for (int pb = 0; pb < 2; pb++) {
                    mma_f16(acc[mt][2 * pb],     ah[mt], bh[pb][0], bh[pb][2]);
                    mma_f16(acc[mt][2 * pb + 1], ah[mt], bh[pb][1], bh[pb][3]);
                }
        }

#pragma unroll
        for (int i = 0; i < 4; i++) hA[i] = hN[i];
    }

    // ---- epilogue: tanh(acc + w1q) * v, reduce N, scatter via rowmap ----
    const int q = lane >> 2;
    float* red = (float*)smem;
    __syncthreads();

#pragma unroll
    for (int mt = 0; mt < 4; mt++) {
        int r_lo = row0 + mw * 64 + mt * 16 + q;
        int r_hi = r_lo + 8;
        int b_lo = g_rowmap[r_lo] >> 11;
        int b_hi = g_rowmap[r_hi] >> 11;
        if (b_lo > BQ - 1) b_lo = BQ - 1;
        if (b_hi > BQ - 1) b_hi = BQ - 1;
        float p0 = 0.f, p1 = 0.f;
#pragma unroll
        for (int n8 = 0; n8 < 4; n8++) {
            int cg = col0 + nwp * 32 + n8 * 8 + (lane & 3) * 2;
            float2 w1a = *(const float2*)(g_w1q + b_lo * DQ + cg);
            float2 w1b = *(const float2*)(g_w1q + b_hi * DQ + cg);
            float2 vv = *(const float2*)(v + cg);
            float* d = acc[mt][n8];
            p0 += fast_tanh(d[0] + w1a.x) * vv.x + fast_tanh(d[1] + w1a.y) * vv.y;
            p1 += fast_tanh(d[2] + w1b.x) * vv.x + fast_tanh(d[3] + w1b.y) * vv.y;
        }
        p0 += __shfl_xor_sync(0xffffffff, p0, 1);
        p0 += __shfl_xor_sync(0xffffffff, p0, 2);
        p1 += __shfl_xor_sync(0xffffffff, p1, 1);
        p1 += __shfl_xor_sync(0xffffffff, p1, 2);
        if ((lane & 3) == 0) {
            int r = mw * 64 + mt * 16 + q;
            red[nwp * 128 + r]     = p0;
            red[nwp * 128 + r + 8] = p1;
        }
    }
    __syncthreads();
    if (tid < 128) {
        float s = 0.f;
#pragma unroll
        for (int w = 0; w < 8; w++) s += red[w * 128 + tid];
        g_partial[blockIdx.x][g_rowmap[row0 + tid]] = s;
    }
}

// ---------------------------------------------------------------------------
// K6: masked softmax (mask int32). One block per batch row.
// ---------------------------------------------------------------------------
__global__ void __launch_bounds__(256) softmax_kernel(const int* __restrict__ mask,
                                                      float* __restrict__ out) {
    const int b = blockIdx.x, tid = threadIdx.x;
    __shared__ float red[256];

    float vals[8];
    float mx = -INFINITY;
#pragma unroll
    for (int t = 0; t < 8; t++) {
        int gi = b * SDIM + tid + t * 256;
        float sc = g_partial[0][gi] + g_partial[1][gi];
        sc = mask[gi] ? sc : -INFINITY;
        vals[t] = sc;
        mx = fmaxf(mx, sc);
    }
    red[tid] = mx;
    __syncthreads();
    for (int o = 128; o; o >>= 1) {
        if (tid < o) red[tid] = fmaxf(red[tid], red[tid + o]);
        __syncthreads();
    }
    mx = red[0];
    __syncthreads();

    float sum = 0.f;
#pragma unroll
    for (int t = 0; t < 8; t++) {
        vals[t] = expf(vals[t] - mx);
        sum += vals[t];
    }
    red[tid] = sum;
    __syncthreads();
    for (int o = 128; o; o >>= 1) {
        if (tid < o) red[tid] += red[tid + o];
        __syncthreads();
    }
    float inv = 1.f / red[0];
#pragma unroll
    for (int t = 0; t < 8; t++) out[b * SDIM + tid + t * 256] = vals[t] * inv;
}

// ---------------------------------------------------------------------------
// Launch: 4 kernels total.
// ---------------------------------------------------------------------------
extern "C" void kernel_launch(void* const* d_in, const int* in_sizes, int n_in,
                              void* d_out, int out_size) {
    const float* query = (const float*)d_in[0];
    const float* keys  = (const float*)d_in[1];
    const int*   mask  = (const int*)d_in[2];
    const float* W1    = (const float*)d_in[3];
    const float* W2    = (const float*)d_in[4];
    const float* v     = (const float*)d_in[5];
    float*       out   = (float*)d_out;

    static bool attr_set = false;
    if (!attr_set) {
        cudaFuncSetAttribute(gemm_kernel, cudaFuncAttributeMaxDynamicSharedMemorySize,
                             SMEM_TOTAL);
        attr_set = true;
    }

    pre1_kernel<<<832, 256>>>(mask, W2, query, W1);
    pre2_kernel<<<256, 256>>>(mask);
    gemm_kernel<<<dim3(2, 512), 512, SMEM_TOTAL>>>(keys, v);
    softmax_kernel<<<BQ, 256>>>(mask, out);
}